// round 5
// baseline (speedup 1.0000x reference)
#include <cuda_runtime.h>
#include <math.h>

#define NNODES 50000
#define KNB 32
#define NLAT 10
#define NB 4
#define PADW 12           // dec_w rows padded 10 -> 12 floats (48B, 16B-aligned)
#define QTOT 12500        // 50000 / 4 float4 quads per row
#define NCHUNK 50
#define QCH 250           // quads per chunk
#define UPB 8

__device__ float g_decw[NNODES * PADW];     // padded dec_w
__device__ float g_part[NCHUNK * 800];      // GEMV partials [chunk][b*200+u]
__device__ float g_Htab[NB * 256];          // sigmoid table per (b, cluster)
__device__ float g_e[NB * NLAT];            // latent e

// ---------------------------------------------------------------- k_prep
__global__ void k_prep(const float* __restrict__ dec_w) {
    int idx = blockIdx.x * blockDim.x + threadIdx.x;
    if (idx < NNODES * PADW) {
        int n = idx / PADW, l = idx - n * PADW;
        g_decw[idx] = (l < NLAT) ? dec_w[n * NLAT + l] : 0.0f;
    }
}

// ---------------------------------------------------------------- k_gemv
// float4-vectorized partial dots: z_raw[b][u] = sum_i x[b][i]*enc1_w[u][i]
__global__ __launch_bounds__(256) void k_gemv(const float* __restrict__ x,
                                              const float* __restrict__ w) {
    int u0 = blockIdx.x * UPB;
    int c  = blockIdx.y;
    int q0 = c * QCH;
    int qend = min(q0 + QCH, QTOT);

    float acc[UPB][NB];
#pragma unroll
    for (int u = 0; u < UPB; u++)
#pragma unroll
        for (int b = 0; b < NB; b++) acc[u][b] = 0.0f;

    for (int q = q0 + (int)threadIdx.x; q < qend; q += 256) {
        float4 xv[NB];
#pragma unroll
        for (int b = 0; b < NB; b++)
            xv[b] = __ldg((const float4*)(x + b * NNODES) + q);
#pragma unroll
        for (int u = 0; u < UPB; u++) {
            float4 wv = __ldg((const float4*)(w + (u0 + u) * NNODES) + q);
#pragma unroll
            for (int b = 0; b < NB; b++) {
                float s = acc[u][b];
                s = fmaf(wv.x, xv[b].x, s);
                s = fmaf(wv.y, xv[b].y, s);
                s = fmaf(wv.z, xv[b].z, s);
                s = fmaf(wv.w, xv[b].w, s);
                acc[u][b] = s;
            }
        }
    }

    __shared__ float sred[UPB * NB * 8];
    int wid = threadIdx.x >> 5, lane = threadIdx.x & 31;
#pragma unroll
    for (int u = 0; u < UPB; u++)
#pragma unroll
        for (int b = 0; b < NB; b++) {
            float v = acc[u][b];
            for (int o = 16; o; o >>= 1) v += __shfl_down_sync(0xffffffffu, v, o);
            if (lane == 0) sred[(u * NB + b) * 8 + wid] = v;
        }
    __syncthreads();
    if (threadIdx.x < UPB * NB) {
        int u = threadIdx.x / NB, b = threadIdx.x - u * NB;
        float s = 0.0f;
#pragma unroll
        for (int q = 0; q < 8; q++) s += sred[threadIdx.x * 8 + q];
        g_part[c * 800 + b * 200 + (u0 + u)] = s;
    }
}

// ---------------------------------------------------------------- k_mid
// finishes z (silu), then e, h1, h2, h3, sigmoid table. Single block (512 thr).
__global__ __launch_bounds__(512) void k_mid(const float* __restrict__ enc1_b,
                      const float* __restrict__ enc2_w, const float* __restrict__ enc2_b,
                      const float* __restrict__ h1_w, const float* __restrict__ h1_b,
                      const float* __restrict__ h2_w, const float* __restrict__ h2_b,
                      const float* __restrict__ h3_w, const float* __restrict__ h3_b) {
    __shared__ float sz[800];
    __shared__ float se[40];
    __shared__ float sh1[256];
    __shared__ float sh2[256];
    int tid = threadIdx.x;

    for (int idx = tid; idx < 800; idx += 512) {
        float s = 0.0f;
#pragma unroll 5
        for (int c = 0; c < NCHUNK; c++) s += g_part[c * 800 + idx];
        int u = idx % 200;
        s += enc1_b[u];
        sz[idx] = s / (1.0f + expf(-s));   // silu
    }
    __syncthreads();

    // e = z @ enc2_w.T : 40 outputs, 8 lanes each summing 25 terms
    if (tid < 320) {
        int g = tid >> 3, r = tid & 7;          // g = b*10+v
        int b = g / 10, v = g - b * 10;
        float s = 0.0f;
        for (int u = r; u < 200; u += 8)
            s = fmaf(sz[b * 200 + u], enc2_w[v * 200 + u], s);
#pragma unroll
        for (int o = 4; o; o >>= 1) s += __shfl_down_sync(0xffffffffu, s, o, 8);
        if (r == 0) {
            s += enc2_b[v];
            se[g] = s;
            g_e[g] = s;
        }
    }
    __syncthreads();

    if (tid < 256) {
        int b = tid >> 6, m = tid & 63;
        float s = h1_b[m];
#pragma unroll
        for (int v = 0; v < 10; v++) s = fmaf(se[b * 10 + v], h1_w[m * 10 + v], s);
        sh1[tid] = s / (1.0f + expf(-s));
    }
    __syncthreads();
    if (tid < 256) {
        int b = tid >> 6, m = tid & 63;
        float s = h2_b[m];
#pragma unroll
        for (int j = 0; j < 64; j++) s = fmaf(sh1[b * 64 + j], h2_w[m * 64 + j], s);
        sh2[tid] = s / (1.0f + expf(-s));
    }
    __syncthreads();
    for (int i = 0; i < 2; i++) {
        int idx = i * 512 + tid;
        int b = idx >> 8, cc = idx & 255;
        float s = h3_b[cc];
#pragma unroll
        for (int j = 0; j < 64; j++) s = fmaf(sh2[b * 64 + j], h3_w[cc * 64 + j], s);
        g_Htab[idx] = 1.0f / (1.0f + expf(-0.005f * s));
    }
}

// ---------------------------------------------------------------- k_main
// 4 threads per node (8 neighbours each), butterfly reduce, then each lane
// owns one batch b. Closed-form unclamped normalization + guarded fallback.
__global__ __launch_bounds__(256) void k_main(const int* __restrict__ nb_id,
                                              const float* __restrict__ nb_dist,
                                              const int* __restrict__ labels,
                                              const float* __restrict__ dec_b,
                                              const float* __restrict__ Bparam,
                                              float* __restrict__ out) {
    int tid = threadIdx.x;
    int sub = tid & 3;
    int node = blockIdx.x * 64 + (tid >> 2);
    bool valid = (node < NNODES);
    int cnode = valid ? node : (NNODES - 1);   // clamp: keep all lanes converged

    float A[NLAT], Bv[NLAT];
#pragma unroll
    for (int l = 0; l < NLAT; l++) { A[l] = 0.0f; Bv[l] = 0.0f; }
    float S0 = 0.0f, d2max = 0.0f;

    const int4*   idp = (const int4*)(nb_id + cnode * KNB) + sub * 2;
    const float4* dp  = (const float4*)(nb_dist + cnode * KNB) + sub * 2;
#pragma unroll
    for (int kq = 0; kq < 2; kq++) {
        int4   iv = __ldg(idp + kq);
        float4 dv = __ldg(dp + kq);
        int   ida[4] = {iv.x, iv.y, iv.z, iv.w};
        float da[4]  = {dv.x, dv.y, dv.z, dv.w};
#pragma unroll
        for (int j = 0; j < 4; j++) {
            float d2 = da[j] * da[j];
            S0 += d2;
            d2max = fmaxf(d2max, d2);
            const float4* rp = (const float4*)(g_decw + ida[j] * PADW);
            float4 r0 = __ldg(rp);
            float4 r1 = __ldg(rp + 1);
            float4 r2 = __ldg(rp + 2);
            float r[NLAT] = {r0.x, r0.y, r0.z, r0.w, r1.x, r1.y, r1.z, r1.w, r2.x, r2.y};
#pragma unroll
            for (int l = 0; l < NLAT; l++) {
                A[l] += r[l];
                Bv[l] = fmaf(d2, r[l], Bv[l]);
            }
        }
    }

    // butterfly reduce across the 4 lanes of this node (xor 1, xor 2)
#pragma unroll
    for (int off = 1; off < 4; off <<= 1) {
#pragma unroll
        for (int l = 0; l < NLAT; l++) {
            A[l]  += __shfl_xor_sync(0xffffffffu, A[l],  off);
            Bv[l] += __shfl_xor_sync(0xffffffffu, Bv[l], off);
        }
        S0 += __shfl_xor_sync(0xffffffffu, S0, off);
        d2max = fmaxf(d2max, __shfl_xor_sync(0xffffffffu, d2max, off));
    }

    // each lane owns batch b = sub
    int b = sub;
    int label = __ldg(&labels[cnode]);
    float Bp = __ldg(Bparam);
    float invB2 = __fdividef(1.0f, Bp * Bp);
    float H = __ldg(&g_Htab[b * 256 + label]);
    float base = 1.0f - 0.5f * H;
    float ib = __fdividef(1.0f, base * base);

    float inv[NLAT];
    {
        float v = invB2 * ib;
        inv[0] = v;
#pragma unroll
        for (int l = 1; l < NLAT; l++) { v *= ib; inv[l] = v; }
    }

    float o = 0.0f;
    if (inv[NLAT - 1] * d2max <= 1.0f) {
        // fast path: no clamping possible for any l (inv monotone in l)
#pragma unroll
        for (int l = 0; l < NLAT; l++) {
            float iw = inv[l];
            float s = fmaf(-iw, S0, (float)KNB);
            float t = fmaf(-iw, Bv[l], A[l]);
            o = fmaf(__ldg(&g_e[b * NLAT + l]), __fdividef(t, s), o);
        }
    } else {
        // exact fallback with clamping (practically never taken)
        float ss[NLAT], tt[NLAT];
#pragma unroll
        for (int l = 0; l < NLAT; l++) { ss[l] = 0.0f; tt[l] = 0.0f; }
        for (int k = 0; k < KNB; k++) {
            int id = __ldg(nb_id + cnode * KNB + k);
            float d = __ldg(nb_dist + cnode * KNB + k);
            float d2 = d * d;
#pragma unroll
            for (int l = 0; l < NLAT; l++) {
                float win = fmaxf(0.0f, fmaf(-inv[l], d2, 1.0f));
                ss[l] += win;
                tt[l] = fmaf(g_decw[id * PADW + l], win, tt[l]);
            }
        }
#pragma unroll
        for (int l = 0; l < NLAT; l++)
            o = fmaf(__ldg(&g_e[b * NLAT + l]), __fdividef(tt[l], ss[l]), o);
    }

    if (valid)
        out[b * NNODES + node] = o + __ldg(&dec_b[node]);
}

// ---------------------------------------------------------------- launch
extern "C" void kernel_launch(void* const* d_in, const int* in_sizes, int n_in,
                              void* d_out, int out_size) {
    const float* x       = (const float*)d_in[0];
    const int*   nb_id   = (const int*)  d_in[1];
    const float* nb_dist = (const float*)d_in[2];
    const int*   labels  = (const int*)  d_in[3];
    const float* enc1_w  = (const float*)d_in[4];
    const float* enc1_b  = (const float*)d_in[5];
    const float* enc2_w  = (const float*)d_in[6];
    const float* enc2_b  = (const float*)d_in[7];
    const float* dec_w   = (const float*)d_in[8];
    const float* dec_b   = (const float*)d_in[9];
    const float* h1_w    = (const float*)d_in[10];
    const float* h1_b    = (const float*)d_in[11];
    const float* h2_w    = (const float*)d_in[12];
    const float* h2_b    = (const float*)d_in[13];
    const float* h3_w    = (const float*)d_in[14];
    const float* h3_b    = (const float*)d_in[15];
    const float* Bp      = (const float*)d_in[16];
    float* out = (float*)d_out;

    k_prep<<<(NNODES * PADW + 255) / 256, 256>>>(dec_w);
    dim3 g(200 / UPB, NCHUNK);
    k_gemv<<<g, 256>>>(x, enc1_w);
    k_mid<<<1, 512>>>(enc1_b, enc2_w, enc2_b, h1_w, h1_b, h2_w, h2_b, h3_w, h3_b);
    k_main<<<(NNODES + 63) / 64, 256>>>(nb_id, nb_dist, labels, dec_b, Bp, out);
}

// round 6
// speedup vs baseline: 1.0911x; 1.0911x over previous
#include <cuda_runtime.h>
#include <math.h>

#define NNODES 50000
#define KNB 32
#define NLAT 10
#define NB 4
#define PADW 12           // dec_w rows padded 10 -> 12 floats (48B, 16B-aligned)
#define QTOT 12500        // 50000 / 4 float4 quads per row
#define NCHUNK 25
#define QCH 500           // quads per chunk
#define UPB 8

__device__ float g_decw[NNODES * PADW];     // padded dec_w
__device__ float g_part[NCHUNK * 800];      // GEMV partials [chunk][b*200+u]
__device__ float g_Htab[NB * 256];          // sigmoid table per (b, cluster)
__device__ float g_e[NB * NLAT];            // latent e

// ---------------------------------------------------------------- k_gemv
// z=0 slice: float4 split-K partial dots  z_raw[b][u] = sum_i x[b][i]*w[u][i]
// z=1 slice: pack dec_w 10 -> 12 floats into g_decw (independent work)
__global__ __launch_bounds__(256) void k_gemv(const float* __restrict__ x,
                                              const float* __restrict__ w,
                                              const float* __restrict__ dec_w) {
    if (blockIdx.z == 1) {
        int t = (blockIdx.y * 25 + blockIdx.x) * 256 + threadIdx.x;
        for (int idx = t; idx < NNODES * PADW; idx += 25 * 25 * 256) {
            int n = idx / PADW, l = idx - n * PADW;
            g_decw[idx] = (l < NLAT) ? dec_w[n * NLAT + l] : 0.0f;
        }
        return;
    }

    int u0 = blockIdx.x * UPB;
    int c  = blockIdx.y;
    int q0 = c * QCH;

    float acc[UPB][NB];
#pragma unroll
    for (int u = 0; u < UPB; u++)
#pragma unroll
        for (int b = 0; b < NB; b++) acc[u][b] = 0.0f;

#pragma unroll 2
    for (int q = q0 + (int)threadIdx.x; q < q0 + QCH; q += 256) {
        float4 xv[NB];
#pragma unroll
        for (int b = 0; b < NB; b++)
            xv[b] = __ldg((const float4*)(x + b * NNODES) + q);
#pragma unroll
        for (int u = 0; u < UPB; u++) {
            float4 wv = __ldg((const float4*)(w + (u0 + u) * NNODES) + q);
#pragma unroll
            for (int b = 0; b < NB; b++) {
                float s = acc[u][b];
                s = fmaf(wv.x, xv[b].x, s);
                s = fmaf(wv.y, xv[b].y, s);
                s = fmaf(wv.z, xv[b].z, s);
                s = fmaf(wv.w, xv[b].w, s);
                acc[u][b] = s;
            }
        }
    }

    __shared__ float sred[UPB * NB * 8];
    int wid = threadIdx.x >> 5, lane = threadIdx.x & 31;
#pragma unroll
    for (int u = 0; u < UPB; u++)
#pragma unroll
        for (int b = 0; b < NB; b++) {
            float v = acc[u][b];
            for (int o = 16; o; o >>= 1) v += __shfl_down_sync(0xffffffffu, v, o);
            if (lane == 0) sred[(u * NB + b) * 8 + wid] = v;
        }
    __syncthreads();
    if (threadIdx.x < UPB * NB) {
        int u = threadIdx.x / NB, b = threadIdx.x - u * NB;
        float s = 0.0f;
#pragma unroll
        for (int q = 0; q < 8; q++) s += sred[threadIdx.x * 8 + q];
        g_part[c * 800 + b * 200 + (u0 + u)] = s;
    }
}

// ---------------------------------------------------------------- k_mid
// finishes z (silu), then e, h1, h2, h3, sigmoid table. Single block (512 thr).
__global__ __launch_bounds__(512) void k_mid(const float* __restrict__ enc1_b,
                      const float* __restrict__ enc2_w, const float* __restrict__ enc2_b,
                      const float* __restrict__ h1_w, const float* __restrict__ h1_b,
                      const float* __restrict__ h2_w, const float* __restrict__ h2_b,
                      const float* __restrict__ h3_w, const float* __restrict__ h3_b) {
    __shared__ float sz[800];
    __shared__ float se[40];
    __shared__ float sh1[256];
    __shared__ float sh2[256];
    int tid = threadIdx.x;

    for (int idx = tid; idx < 800; idx += 512) {
        float s = 0.0f;
#pragma unroll 5
        for (int c = 0; c < NCHUNK; c++) s += g_part[c * 800 + idx];
        int u = idx % 200;
        s += enc1_b[u];
        sz[idx] = s / (1.0f + expf(-s));   // silu
    }
    __syncthreads();

    // e = z @ enc2_w.T : 40 outputs, 8 lanes each summing 25 terms
    if (tid < 320) {
        int g = tid >> 3, r = tid & 7;          // g = b*10+v
        int b = g / 10, v = g - b * 10;
        float s = 0.0f;
        for (int u = r; u < 200; u += 8)
            s = fmaf(sz[b * 200 + u], enc2_w[v * 200 + u], s);
#pragma unroll
        for (int o = 4; o; o >>= 1) s += __shfl_down_sync(0xffffffffu, s, o, 8);
        if (r == 0) {
            s += enc2_b[v];
            se[g] = s;
            g_e[g] = s;
        }
    }
    __syncthreads();

    if (tid < 256) {
        int b = tid >> 6, m = tid & 63;
        float s = h1_b[m];
#pragma unroll
        for (int v = 0; v < 10; v++) s = fmaf(se[b * 10 + v], h1_w[m * 10 + v], s);
        sh1[tid] = s / (1.0f + expf(-s));
    }
    __syncthreads();
    if (tid < 256) {
        int b = tid >> 6, m = tid & 63;
        float s = h2_b[m];
#pragma unroll
        for (int j = 0; j < 64; j++) s = fmaf(sh1[b * 64 + j], h2_w[m * 64 + j], s);
        sh2[tid] = s / (1.0f + expf(-s));
    }
    __syncthreads();
    for (int i = 0; i < 2; i++) {
        int idx = i * 512 + tid;
        int b = idx >> 8, cc = idx & 255;
        float s = h3_b[cc];
#pragma unroll
        for (int j = 0; j < 64; j++) s = fmaf(sh2[b * 64 + j], h3_w[cc * 64 + j], s);
        g_Htab[idx] = 1.0f / (1.0f + expf(-0.005f * s));
    }
}

// ---------------------------------------------------------------- k_main
// 4 threads per node (8 neighbours each), butterfly reduce, then each lane
// owns one batch b. Register-capped for 5 blocks/SM occupancy.
__global__ __launch_bounds__(256, 5) void k_main(const int* __restrict__ nb_id,
                                              const float* __restrict__ nb_dist,
                                              const int* __restrict__ labels,
                                              const float* __restrict__ dec_b,
                                              const float* __restrict__ Bparam,
                                              float* __restrict__ out) {
    int tid = threadIdx.x;
    int sub = tid & 3;
    int node = blockIdx.x * 64 + (tid >> 2);
    bool valid = (node < NNODES);
    int cnode = valid ? node : (NNODES - 1);   // clamp: keep all lanes converged

    float A[NLAT], Bv[NLAT];
#pragma unroll
    for (int l = 0; l < NLAT; l++) { A[l] = 0.0f; Bv[l] = 0.0f; }
    float S0 = 0.0f, d2max = 0.0f;

    const int4*   idp = (const int4*)(nb_id + cnode * KNB) + sub * 2;
    const float4* dp  = (const float4*)(nb_dist + cnode * KNB) + sub * 2;
#pragma unroll
    for (int kq = 0; kq < 2; kq++) {
        int4   iv = __ldg(idp + kq);
        float4 dv = __ldg(dp + kq);
        int   ida[4] = {iv.x, iv.y, iv.z, iv.w};
        float da[4]  = {dv.x, dv.y, dv.z, dv.w};
#pragma unroll
        for (int j = 0; j < 4; j++) {
            float d2 = da[j] * da[j];
            S0 += d2;
            d2max = fmaxf(d2max, d2);
            const float4* rp = (const float4*)(g_decw + ida[j] * PADW);
            float4 r0 = __ldg(rp);
            float4 r1 = __ldg(rp + 1);
            float4 r2 = __ldg(rp + 2);
            float r[NLAT] = {r0.x, r0.y, r0.z, r0.w, r1.x, r1.y, r1.z, r1.w, r2.x, r2.y};
#pragma unroll
            for (int l = 0; l < NLAT; l++) {
                A[l] += r[l];
                Bv[l] = fmaf(d2, r[l], Bv[l]);
            }
        }
    }

    // butterfly reduce across the 4 lanes of this node (xor 1, xor 2)
#pragma unroll
    for (int off = 1; off < 4; off <<= 1) {
#pragma unroll
        for (int l = 0; l < NLAT; l++) {
            A[l]  += __shfl_xor_sync(0xffffffffu, A[l],  off);
            Bv[l] += __shfl_xor_sync(0xffffffffu, Bv[l], off);
        }
        S0 += __shfl_xor_sync(0xffffffffu, S0, off);
        d2max = fmaxf(d2max, __shfl_xor_sync(0xffffffffu, d2max, off));
    }

    // each lane owns batch b = sub
    int b = sub;
    int label = __ldg(&labels[cnode]);
    float Bp = __ldg(Bparam);
    float invB2 = __fdividef(1.0f, Bp * Bp);
    float H = __ldg(&g_Htab[b * 256 + label]);
    float base = 1.0f - 0.5f * H;
    float ib = __fdividef(1.0f, base * base);

    // inv[l] = invB2 * ib^(l+1);  guard uses inv[9] = invB2 * ib^10
    float ib2 = ib * ib;
    float ib4 = ib2 * ib2;
    float inv9 = invB2 * ib4 * ib4 * ib2;

    float o = 0.0f;
    if (inv9 * d2max <= 1.0f) {
        // fast path: no clamping possible for any l (inv monotone in l)
        float iw = invB2;
#pragma unroll
        for (int l = 0; l < NLAT; l++) {
            iw *= ib;
            float s = fmaf(-iw, S0, (float)KNB);
            float t = fmaf(-iw, Bv[l], A[l]);
            o = fmaf(__ldg(&g_e[b * NLAT + l]), __fdividef(t, s), o);
        }
    } else {
        // exact fallback with clamping (practically never taken; not unrolled)
        float iw = invB2;
        for (int l = 0; l < NLAT; l++) {
            iw *= ib;
            float ss = 0.0f, tt = 0.0f;
            for (int k = 0; k < KNB; k++) {
                int id = __ldg(nb_id + cnode * KNB + k);
                float d = __ldg(nb_dist + cnode * KNB + k);
                float d2 = d * d;
                float win = fmaxf(0.0f, fmaf(-iw, d2, 1.0f));
                ss += win;
                tt = fmaf(g_decw[id * PADW + l], win, tt);
            }
            o = fmaf(__ldg(&g_e[b * NLAT + l]), __fdividef(tt, ss), o);
        }
    }

    if (valid)
        out[b * NNODES + node] = o + __ldg(&dec_b[node]);
}

// ---------------------------------------------------------------- launch
extern "C" void kernel_launch(void* const* d_in, const int* in_sizes, int n_in,
                              void* d_out, int out_size) {
    const float* x       = (const float*)d_in[0];
    const int*   nb_id   = (const int*)  d_in[1];
    const float* nb_dist = (const float*)d_in[2];
    const int*   labels  = (const int*)  d_in[3];
    const float* enc1_w  = (const float*)d_in[4];
    const float* enc1_b  = (const float*)d_in[5];
    const float* enc2_w  = (const float*)d_in[6];
    const float* enc2_b  = (const float*)d_in[7];
    const float* dec_w   = (const float*)d_in[8];
    const float* dec_b   = (const float*)d_in[9];
    const float* h1_w    = (const float*)d_in[10];
    const float* h1_b    = (const float*)d_in[11];
    const float* h2_w    = (const float*)d_in[12];
    const float* h2_b    = (const float*)d_in[13];
    const float* h3_w    = (const float*)d_in[14];
    const float* h3_b    = (const float*)d_in[15];
    const float* Bp      = (const float*)d_in[16];
    float* out = (float*)d_out;

    dim3 g(200 / UPB, NCHUNK, 2);   // z=0 gemv, z=1 dec_w pack
    k_gemv<<<g, 256>>>(x, enc1_w, dec_w);
    k_mid<<<1, 512>>>(enc1_b, enc2_w, enc2_b, h1_w, h1_b, h2_w, h2_b, h3_w, h3_b);
    k_main<<<(NNODES + 63) / 64, 256>>>(nb_id, nb_dist, labels, dec_b, Bp, out);
}

// round 7
// speedup vs baseline: 1.1710x; 1.0732x over previous
#include <cuda_runtime.h>
#include <cuda_fp16.h>
#include <math.h>

#define NNODES 50000
#define KNB 32
#define NLAT 10
#define NB 4
#define NCHUNK 25
#define QCH 500           // float4 quads per gemv chunk (25*500 = 12500 = 50000/4)
#define UPB 8
#define GEMV_BLOCKS 625   // (200/UPB) * NCHUNK
#define GATHER_BLOCKS 782 // ceil(50000 / 64)
#define TOT_BLOCKS (GEMV_BLOCKS + GATHER_BLOCKS)

__device__ uint4 g_decwr[NNODES * 2];       // fp16-packed dec_w rows (32B/row)
__device__ float g_part[NCHUNK * 800];      // GEMV partials [chunk][b*200+u]
__device__ float g_Htab[NB * 256];          // sigmoid table per (b, cluster)
__device__ float g_e[NB * NLAT];            // latent e
__device__ float g_stats[NNODES * 24];      // per-node A[10],Bv[10],S0,d2max,pad

__device__ __forceinline__ float2 h2f(unsigned u) {
    __half2 h = *reinterpret_cast<__half2*>(&u);
    return __half22float2(h);
}

// ---------------------------------------------------------------- k_pack
// dec_w [n][10] fp32 -> fp16 packed rows of 16 halves (32B, 16B-aligned)
__global__ __launch_bounds__(256) void k_pack(const float* __restrict__ dec_w) {
    int n = blockIdx.x * 256 + threadIdx.x;
    if (n >= NNODES) return;
    const float2* rp = (const float2*)(dec_w + n * NLAT);   // 40B rows, 8B aligned
    float2 a = __ldg(rp), b = __ldg(rp + 1), c = __ldg(rp + 2),
           d = __ldg(rp + 3), e = __ldg(rp + 4);
    __half2 p0 = __float22half2_rn(a), p1 = __float22half2_rn(b),
            p2 = __float22half2_rn(c), p3 = __float22half2_rn(d),
            p4 = __float22half2_rn(e);
    uint4 lo = make_uint4(*(unsigned*)&p0, *(unsigned*)&p1,
                          *(unsigned*)&p2, *(unsigned*)&p3);
    g_decwr[2 * n] = lo;
    ((uint2*)g_decwr)[4 * n + 2] = make_uint2(*(unsigned*)&p4, 0u);
}

// ---------------------------------------------------------------- k_fused
// Bresenham-interleaved block types so gemv (DRAM-bound) and gather
// (L1/L2-bound) blocks are co-resident on every SM.
__global__ __launch_bounds__(256) void k_fused(const float* __restrict__ x,
                                               const float* __restrict__ w,
                                               const int* __restrict__ nb_id,
                                               const float* __restrict__ nb_dist) {
    int bid = blockIdx.x;
    int g0 = (bid * GEMV_BLOCKS) / TOT_BLOCKS;
    int g1 = ((bid + 1) * GEMV_BLOCKS) / TOT_BLOCKS;

    if (g1 > g0) {
        // ------------------------------------------------ gemv block
        int gi = g0;
        int u0 = (gi % 25) * UPB;
        int c  = gi / 25;
        int q0 = c * QCH;

        float acc[UPB][NB];
#pragma unroll
        for (int u = 0; u < UPB; u++)
#pragma unroll
            for (int b = 0; b < NB; b++) acc[u][b] = 0.0f;

        for (int q = q0 + (int)threadIdx.x; q < q0 + QCH; q += 256) {
            float4 xv[NB];
#pragma unroll
            for (int b = 0; b < NB; b++)
                xv[b] = __ldg((const float4*)(x + b * NNODES) + q);
#pragma unroll
            for (int u = 0; u < UPB; u++) {
                float4 wv = __ldg((const float4*)(w + (u0 + u) * NNODES) + q);
#pragma unroll
                for (int b = 0; b < NB; b++) {
                    float s = acc[u][b];
                    s = fmaf(wv.x, xv[b].x, s);
                    s = fmaf(wv.y, xv[b].y, s);
                    s = fmaf(wv.z, xv[b].z, s);
                    s = fmaf(wv.w, xv[b].w, s);
                    acc[u][b] = s;
                }
            }
        }

        __shared__ float sred[UPB * NB * 8];
        int wid = threadIdx.x >> 5, lane = threadIdx.x & 31;
#pragma unroll
        for (int u = 0; u < UPB; u++)
#pragma unroll
            for (int b = 0; b < NB; b++) {
                float v = acc[u][b];
                for (int o = 16; o; o >>= 1) v += __shfl_down_sync(0xffffffffu, v, o);
                if (lane == 0) sred[(u * NB + b) * 8 + wid] = v;
            }
        __syncthreads();
        if (threadIdx.x < UPB * NB) {
            int u = threadIdx.x / NB, b = threadIdx.x - u * NB;
            float s = 0.0f;
#pragma unroll
            for (int q = 0; q < 8; q++) s += sred[threadIdx.x * 8 + q];
            g_part[c * 800 + b * 200 + (u0 + u)] = s;
        }
        return;
    }

    // ---------------------------------------------------- gather block
    int gidx = bid - g0;
    int tid = threadIdx.x;
    int sub = tid & 3;
    int node = gidx * 64 + (tid >> 2);
    bool valid = (node < NNODES);
    int cnode = valid ? node : (NNODES - 1);

    float A[NLAT], Bv[NLAT];
#pragma unroll
    for (int l = 0; l < NLAT; l++) { A[l] = 0.0f; Bv[l] = 0.0f; }
    float S0 = 0.0f, d2max = 0.0f;

    const int4*   idp = (const int4*)(nb_id + cnode * KNB) + sub * 2;
    const float4* dp  = (const float4*)(nb_dist + cnode * KNB) + sub * 2;
#pragma unroll
    for (int kq = 0; kq < 2; kq++) {
        int4   iv = __ldg(idp + kq);
        float4 dv = __ldg(dp + kq);
        int   ida[4] = {iv.x, iv.y, iv.z, iv.w};
        float da[4]  = {dv.x, dv.y, dv.z, dv.w};
#pragma unroll
        for (int j = 0; j < 4; j++) {
            float d2 = da[j] * da[j];
            S0 += d2;
            d2max = fmaxf(d2max, d2);
            uint4 lo = __ldg(&g_decwr[2 * ida[j]]);
            uint2 hi = __ldg((const uint2*)g_decwr + 4 * ida[j] + 2);
            float2 f0 = h2f(lo.x), f1 = h2f(lo.y), f2 = h2f(lo.z),
                   f3 = h2f(lo.w), f4 = h2f(hi.x);
            float r[NLAT] = {f0.x, f0.y, f1.x, f1.y, f2.x,
                             f2.y, f3.x, f3.y, f4.x, f4.y};
#pragma unroll
            for (int l = 0; l < NLAT; l++) {
                A[l] += r[l];
                Bv[l] = fmaf(d2, r[l], Bv[l]);
            }
        }
    }

    // butterfly reduce across the 4 lanes of this node
#pragma unroll
    for (int off = 1; off < 4; off <<= 1) {
#pragma unroll
        for (int l = 0; l < NLAT; l++) {
            A[l]  += __shfl_xor_sync(0xffffffffu, A[l],  off);
            Bv[l] += __shfl_xor_sync(0xffffffffu, Bv[l], off);
        }
        S0 += __shfl_xor_sync(0xffffffffu, S0, off);
        d2max = fmaxf(d2max, __shfl_xor_sync(0xffffffffu, d2max, off));
    }

    if (sub == 0 && valid) {
        float4* sp = (float4*)(g_stats + node * 24);
        sp[0] = make_float4(A[0], A[1], A[2], A[3]);
        sp[1] = make_float4(A[4], A[5], A[6], A[7]);
        sp[2] = make_float4(A[8], A[9], Bv[0], Bv[1]);
        sp[3] = make_float4(Bv[2], Bv[3], Bv[4], Bv[5]);
        sp[4] = make_float4(Bv[6], Bv[7], Bv[8], Bv[9]);
        sp[5] = make_float4(S0, d2max, 0.0f, 0.0f);
    }
}

// ---------------------------------------------------------------- k_mid
__global__ __launch_bounds__(512) void k_mid(const float* __restrict__ enc1_b,
                      const float* __restrict__ enc2_w, const float* __restrict__ enc2_b,
                      const float* __restrict__ h1_w, const float* __restrict__ h1_b,
                      const float* __restrict__ h2_w, const float* __restrict__ h2_b,
                      const float* __restrict__ h3_w, const float* __restrict__ h3_b) {
    __shared__ float sz[800];
    __shared__ float se[40];
    __shared__ float sh1[256];
    __shared__ float sh2[256];
    int tid = threadIdx.x;

    for (int idx = tid; idx < 800; idx += 512) {
        float s = 0.0f;
#pragma unroll 5
        for (int c = 0; c < NCHUNK; c++) s += g_part[c * 800 + idx];
        int u = idx % 200;
        s += enc1_b[u];
        sz[idx] = s / (1.0f + expf(-s));   // silu
    }
    __syncthreads();

    if (tid < 320) {
        int g = tid >> 3, r = tid & 7;
        int b = g / 10, v = g - b * 10;
        float s = 0.0f;
        for (int u = r; u < 200; u += 8)
            s = fmaf(sz[b * 200 + u], enc2_w[v * 200 + u], s);
#pragma unroll
        for (int o = 4; o; o >>= 1) s += __shfl_down_sync(0xffffffffu, s, o, 8);
        if (r == 0) {
            s += enc2_b[v];
            se[g] = s;
            g_e[g] = s;
        }
    }
    __syncthreads();

    if (tid < 256) {
        int b = tid >> 6, m = tid & 63;
        float s = h1_b[m];
#pragma unroll
        for (int v = 0; v < 10; v++) s = fmaf(se[b * 10 + v], h1_w[m * 10 + v], s);
        sh1[tid] = s / (1.0f + expf(-s));
    }
    __syncthreads();
    if (tid < 256) {
        int b = tid >> 6, m = tid & 63;
        float s = h2_b[m];
#pragma unroll
        for (int j = 0; j < 64; j++) s = fmaf(sh1[b * 64 + j], h2_w[m * 64 + j], s);
        sh2[tid] = s / (1.0f + expf(-s));
    }
    __syncthreads();
    for (int i = 0; i < 2; i++) {
        int idx = i * 512 + tid;
        int b = idx >> 8, cc = idx & 255;
        float s = h3_b[cc];
#pragma unroll
        for (int j = 0; j < 64; j++) s = fmaf(sh2[b * 64 + j], h3_w[cc * 64 + j], s);
        g_Htab[idx] = 1.0f / (1.0f + expf(-0.005f * s));
    }
}

// ---------------------------------------------------------------- k_final
// per node: combine stats with H/e; closed-form unless clamping possible.
__global__ __launch_bounds__(256) void k_final(const int* __restrict__ labels,
                                               const float* __restrict__ dec_b,
                                               const float* __restrict__ Bparam,
                                               const int* __restrict__ nb_id,
                                               const float* __restrict__ nb_dist,
                                               const float* __restrict__ dec_w,
                                               float* __restrict__ out) {
    int node = blockIdx.x * 256 + threadIdx.x;
    if (node >= NNODES) return;

    const float4* sp = (const float4*)(g_stats + node * 24);
    float4 s0 = __ldg(sp),     s1 = __ldg(sp + 1), s2 = __ldg(sp + 2),
           s3 = __ldg(sp + 3), s4 = __ldg(sp + 4), s5 = __ldg(sp + 5);
    float A[NLAT]  = {s0.x, s0.y, s0.z, s0.w, s1.x, s1.y, s1.z, s1.w, s2.x, s2.y};
    float Bv[NLAT] = {s2.z, s2.w, s3.x, s3.y, s3.z, s3.w, s4.x, s4.y, s4.z, s4.w};
    float S0 = s5.x, d2max = s5.y;

    int label = __ldg(&labels[node]);
    float Bp = __ldg(Bparam);
    float invB2 = __fdividef(1.0f, Bp * Bp);
    float db = __ldg(&dec_b[node]);

#pragma unroll
    for (int b = 0; b < NB; b++) {
        float H = __ldg(&g_Htab[b * 256 + label]);
        float base = 1.0f - 0.5f * H;
        float ib = __fdividef(1.0f, base * base);
        float ib2 = ib * ib;
        float ib4 = ib2 * ib2;
        float inv9 = invB2 * ib4 * ib4 * ib2;

        float o = 0.0f;
        if (inv9 * d2max <= 1.0f) {
            float iw = invB2;
#pragma unroll
            for (int l = 0; l < NLAT; l++) {
                iw *= ib;
                float s = fmaf(-iw, S0, (float)KNB);
                float t = fmaf(-iw, Bv[l], A[l]);
                o = fmaf(__ldg(&g_e[b * NLAT + l]), __fdividef(t, s), o);
            }
        } else {
            // exact fallback with clamping (fp32 dec_w; practically never taken)
            float iw = invB2;
            for (int l = 0; l < NLAT; l++) {
                iw *= ib;
                float ss = 0.0f, tt = 0.0f;
                for (int k = 0; k < KNB; k++) {
                    int id = __ldg(nb_id + node * KNB + k);
                    float d = __ldg(nb_dist + node * KNB + k);
                    float d2 = d * d;
                    float win = fmaxf(0.0f, fmaf(-iw, d2, 1.0f));
                    ss += win;
                    tt = fmaf(__ldg(&dec_w[id * NLAT + l]), win, tt);
                }
                o = fmaf(__ldg(&g_e[b * NLAT + l]), __fdividef(tt, ss), o);
            }
        }
        out[b * NNODES + node] = o + db;
    }
}

// ---------------------------------------------------------------- launch
extern "C" void kernel_launch(void* const* d_in, const int* in_sizes, int n_in,
                              void* d_out, int out_size) {
    const float* x       = (const float*)d_in[0];
    const int*   nb_id   = (const int*)  d_in[1];
    const float* nb_dist = (const float*)d_in[2];
    const int*   labels  = (const int*)  d_in[3];
    const float* enc1_w  = (const float*)d_in[4];
    const float* enc1_b  = (const float*)d_in[5];
    const float* enc2_w  = (const float*)d_in[6];
    const float* enc2_b  = (const float*)d_in[7];
    const float* dec_w   = (const float*)d_in[8];
    const float* dec_b   = (const float*)d_in[9];
    const float* h1_w    = (const float*)d_in[10];
    const float* h1_b    = (const float*)d_in[11];
    const float* h2_w    = (const float*)d_in[12];
    const float* h2_b    = (const float*)d_in[13];
    const float* h3_w    = (const float*)d_in[14];
    const float* h3_b    = (const float*)d_in[15];
    const float* Bp      = (const float*)d_in[16];
    float* out = (float*)d_out;

    k_pack<<<(NNODES + 255) / 256, 256>>>(dec_w);
    k_fused<<<TOT_BLOCKS, 256>>>(x, enc1_w, nb_id, nb_dist);
    k_mid<<<1, 512>>>(enc1_b, enc2_w, enc2_b, h1_w, h1_b, h2_w, h2_b, h3_w, h3_b);
    k_final<<<(NNODES + 255) / 256, 256>>>(labels, dec_b, Bp, nb_id, nb_dist, dec_w, out);
}